// round 1
// baseline (speedup 1.0000x reference)
#include <cuda_runtime.h>
#include <math.h>

// Problem constants
#define PB 32
#define PL 256
#define PD 256
#define PH 256
#define PE 8
#define PNL 4
#define PK 4
#define NSEQ (PB*PE)          // 256 sequences
#define MROWS (PB*PE*PL)      // 65536 GEMM rows

// Scratch (static device memory; no allocations allowed)
__device__ float g_ln[PB*PL*PD];          // 8MB
__device__ float g_conv[PB*PL*PD];        // 8MB
__device__ float g_pre[MROWS*PH];         // 64MB
__device__ float g_ys[MROWS*PH];          // 64MB
__device__ float g_whhT[PNL*PH*PH];       // 1MB  (W_hh transposed: [l][f][h])

// ---------------------------------------------------------------------------
// LayerNorm: one block per token (B*L), 256 threads
// ---------------------------------------------------------------------------
__global__ __launch_bounds__(256) void ln_kernel(
    const float* __restrict__ x, const float* __restrict__ g,
    const float* __restrict__ bb, float* __restrict__ out)
{
    int tok = blockIdx.x;
    int t = threadIdx.x;
    float v = x[tok*256 + t];
    float s1 = v, s2 = v*v;
    #pragma unroll
    for (int o = 16; o > 0; o >>= 1) {
        s1 += __shfl_xor_sync(0xffffffffu, s1, o);
        s2 += __shfl_xor_sync(0xffffffffu, s2, o);
    }
    __shared__ float a1[8], a2[8];
    int w = t >> 5, ln = t & 31;
    if (ln == 0) { a1[w] = s1; a2[w] = s2; }
    __syncthreads();
    if (w == 0) {
        float b1 = (ln < 8) ? a1[ln] : 0.f;
        float b2 = (ln < 8) ? a2[ln] : 0.f;
        #pragma unroll
        for (int o = 4; o > 0; o >>= 1) {
            b1 += __shfl_xor_sync(0xffffffffu, b1, o);
            b2 += __shfl_xor_sync(0xffffffffu, b2, o);
        }
        if (ln == 0) { a1[0] = b1; a2[0] = b2; }
    }
    __syncthreads();
    float mean = a1[0] * (1.f/256.f);
    float var  = a2[0] * (1.f/256.f) - mean*mean;
    out[tok*256 + t] = (v - mean) * rsqrtf(var + 1e-5f) * g[t] + bb[t];
}

// ---------------------------------------------------------------------------
// Depthwise causal conv1d (K=4, left pad 3): one block per token
// ---------------------------------------------------------------------------
__global__ __launch_bounds__(256) void conv_kernel(
    const float* __restrict__ ln, const float* __restrict__ w,
    const float* __restrict__ cb, float* __restrict__ out)
{
    int tok = blockIdx.x;
    int d = threadIdx.x;
    int b = tok >> 8, l = tok & 255;
    float acc = cb[d];
    #pragma unroll
    for (int k = 0; k < PK; k++) {
        int ls = l - 3 + k;
        if (ls >= 0) acc += ln[(b*256 + ls)*256 + d] * w[d*PK + k];
    }
    out[tok*256 + d] = acc;
}

// ---------------------------------------------------------------------------
// Transpose W_hh -> W_hh^T per layer: whhT[l][f][h] = whh[l][h][f]
// ---------------------------------------------------------------------------
__global__ __launch_bounds__(256) void transpose_whh(
    const float* __restrict__ whh, float* __restrict__ whhT)
{
    int idx = blockIdx.x*256 + threadIdx.x;   // NL*256*256 total
    int l = idx >> 16;
    int f = (idx >> 8) & 255;
    int h = idx & 255;
    whhT[idx] = whh[(l*256 + h)*256 + f];
}

// ---------------------------------------------------------------------------
// Input projection GEMM:
//   pre[m,h] = (sum_f X[m,f]*r[e,f]*W[h,f]) * s[e,h] + bias[h]
//   m = (b*E + e)*L + l ; for layer0, X row is conv[b,l,:]
// 128x128x16 tile, 256 threads, 8x8 per thread
// ---------------------------------------------------------------------------
#define BM 128
#define BN 128
#define BK 16

__global__ __launch_bounds__(256) void gemm_pre(
    const float* __restrict__ X, const float* __restrict__ Wl,
    const float* __restrict__ rl, const float* __restrict__ sl,
    const float* __restrict__ bl, float* __restrict__ out, int layer0)
{
    __shared__ float As[BK][BM+4];
    __shared__ float Bs[BK][BN+4];
    int m0 = blockIdx.y * BM;
    int n0 = blockIdx.x * BN;
    int tid = threadIdx.x;
    int tm0 = (tid >> 4) * 8;
    int tn0 = (tid & 15) * 8;
    float acc[8][8];
    #pragma unroll
    for (int i = 0; i < 8; i++)
        #pragma unroll
        for (int j = 0; j < 8; j++) acc[i][j] = 0.f;

    for (int k0 = 0; k0 < 256; k0 += BK) {
        // Load A and B tiles (512 float4 each; 2 per thread per tile)
        #pragma unroll
        for (int v = tid; v < 512; v += 256) {
            int row = v >> 2;
            int kq  = (v & 3) * 4;
            // ---- A ----
            int m = m0 + row;
            int e = (m >> 8) & 7;
            const float* xrow;
            if (layer0) {
                int b = m >> 11;
                int l = m & 255;
                xrow = X + (size_t)(b*256 + l) * 256;
            } else {
                xrow = X + (size_t)m * 256;
            }
            float4 xv = *(const float4*)(xrow + k0 + kq);
            float4 rv = *(const float4*)(rl + e*256 + k0 + kq);
            As[kq  ][row] = xv.x * rv.x;
            As[kq+1][row] = xv.y * rv.y;
            As[kq+2][row] = xv.z * rv.z;
            As[kq+3][row] = xv.w * rv.w;
            // ---- B:  Bs[k][n] = W[(n0+n)*256 + k0+k] ----
            int n = n0 + row;
            float4 wv = *(const float4*)(Wl + (size_t)n*256 + k0 + kq);
            Bs[kq  ][row] = wv.x;
            Bs[kq+1][row] = wv.y;
            Bs[kq+2][row] = wv.z;
            Bs[kq+3][row] = wv.w;
        }
        __syncthreads();
        #pragma unroll
        for (int k = 0; k < BK; k++) {
            float a[8], b[8];
            *(float4*)(a)   = *(const float4*)&As[k][tm0];
            *(float4*)(a+4) = *(const float4*)&As[k][tm0+4];
            *(float4*)(b)   = *(const float4*)&Bs[k][tn0];
            *(float4*)(b+4) = *(const float4*)&Bs[k][tn0+4];
            #pragma unroll
            for (int i = 0; i < 8; i++)
                #pragma unroll
                for (int j = 0; j < 8; j++)
                    acc[i][j] += a[i] * b[j];
        }
        __syncthreads();
    }

    // Epilogue: * s[e,h] + bias[h]
    #pragma unroll
    for (int i = 0; i < 8; i++) {
        int m = m0 + tm0 + i;
        int e = (m >> 8) & 7;
        #pragma unroll
        for (int j = 0; j < 8; j += 4) {
            int n = n0 + tn0 + j;
            float4 sv = *(const float4*)(sl + e*256 + n);
            float4 bv = *(const float4*)(bl + n);
            float4 o;
            o.x = acc[i][j  ] * sv.x + bv.x;
            o.y = acc[i][j+1] * sv.y + bv.y;
            o.z = acc[i][j+2] * sv.z + bv.z;
            o.w = acc[i][j+3] * sv.w + bv.w;
            *(float4*)(out + (size_t)m*256 + n) = o;
        }
    }
}

// ---------------------------------------------------------------------------
// Recurrence: persistent kernel. 128 blocks x 256 threads, 2 sequences/block.
//   h_t[k] = tanh(pre_t[k] + sum_j h_{t-1}[j] * WhhT[j][k])
// WhhT rows [0,192) cached in smem; rows [192,256) held in registers
// (loop-invariant across all 256 steps -> zero global weight traffic in loop).
// ---------------------------------------------------------------------------
#define SROWS 192
#define RROWS 64
#define RNN_SMEM (SROWS*256*4 + 256*8)

__global__ __launch_bounds__(256) void rnn_kernel(
    const float* __restrict__ pre, const float* __restrict__ wT,
    float* __restrict__ ys, float* __restrict__ hlast)
{
    extern __shared__ float sm[];
    float*  sW  = sm;                               // [SROWS][256]
    float2* hsv = (float2*)(sm + SROWS*256);        // [256] (h for 2 seqs)
    int t = threadIdx.x;
    int q0 = blockIdx.x * 2;

    // Load smem weights (48 float4 per thread)
    const float4* wT4 = (const float4*)wT;
    float4* sW4 = (float4*)sW;
    for (int i = t; i < SROWS*64; i += 256) sW4[i] = wT4[i];

    // Register-resident weight rows [192,256): wreg[j] = WhhT[192+j][t]
    float wreg[RROWS];
    #pragma unroll
    for (int j = 0; j < RROWS; j++)
        wreg[j] = wT[(SROWS + j)*256 + t];

    hsv[t] = make_float2(0.f, 0.f);
    __syncthreads();

    const float* pre0 = pre + (size_t)q0 * PL * PH;
    const float* pre1 = pre0 + PL*PH;
    float* ys0 = ys + (size_t)q0 * PL * PH;
    float* ys1 = ys0 + PL*PH;

    for (int l = 0; l < PL; l++) {
        float acc0 = pre0[l*256 + t];
        float acc1 = pre1[l*256 + t];
        #pragma unroll 8
        for (int f = 0; f < SROWS; f += 2) {
            float4 hp = *(const float4*)(hsv + f);   // h[f] (2 seqs), h[f+1] (2 seqs)
            float w0 = sW[f*256 + t];
            float w1 = sW[f*256 + 256 + t];
            acc0 += w0*hp.x; acc1 += w0*hp.y;
            acc0 += w1*hp.z; acc1 += w1*hp.w;
        }
        #pragma unroll
        for (int j = 0; j < RROWS; j += 2) {
            float4 hp = *(const float4*)(hsv + SROWS + j);
            acc0 += wreg[j  ]*hp.x; acc1 += wreg[j  ]*hp.y;
            acc0 += wreg[j+1]*hp.z; acc1 += wreg[j+1]*hp.w;
        }
        float h0 = tanhf(acc0);
        float h1 = tanhf(acc1);
        ys0[l*256 + t] = h0;
        ys1[l*256 + t] = h1;
        __syncthreads();              // all reads of old h done
        hsv[t] = make_float2(h0, h1);
        __syncthreads();              // new h visible
    }

    if (hlast) {
        float2 hf = hsv[t];
        hlast[q0*256 + t]     = hf.x;
        hlast[(q0+1)*256 + t] = hf.y;
    }
}

// ---------------------------------------------------------------------------
extern "C" void kernel_launch(void* const* d_in, const int* in_sizes, int n_in,
                              void* d_out, int out_size)
{
    const float* x      = (const float*)d_in[0];
    const float* conv_w = (const float*)d_in[1];
    const float* conv_b = (const float*)d_in[2];
    const float* ln_g   = (const float*)d_in[3];
    const float* ln_b   = (const float*)d_in[4];
    const float* W_ih   = (const float*)d_in[5];
    const float* W_hh   = (const float*)d_in[6];
    const float* r      = (const float*)d_in[7];
    const float* s      = (const float*)d_in[8];
    const float* b      = (const float*)d_in[9];

    float* out = (float*)d_out;

    // Scratch pointers from device symbols
    static float *p_ln = nullptr, *p_conv = nullptr, *p_pre = nullptr,
                 *p_ys = nullptr, *p_whhT = nullptr;
    static bool attr_done = false;
    if (!p_ln) {
        cudaGetSymbolAddress((void**)&p_ln,   g_ln);
        cudaGetSymbolAddress((void**)&p_conv, g_conv);
        cudaGetSymbolAddress((void**)&p_pre,  g_pre);
        cudaGetSymbolAddress((void**)&p_ys,   g_ys);
        cudaGetSymbolAddress((void**)&p_whhT, g_whhT);
    }
    if (!attr_done) {
        cudaFuncSetAttribute(rnn_kernel,
                             cudaFuncAttributeMaxDynamicSharedMemorySize,
                             RNN_SMEM);
        attr_done = true;
    }

    ln_kernel<<<PB*PL, 256>>>(x, ln_g, ln_b, p_ln);
    conv_kernel<<<PB*PL, 256>>>(p_ln, conv_w, conv_b, p_conv);
    transpose_whh<<<PNL*256, 256>>>(W_hh, p_whhT);

    const size_t hN    = (size_t)MROWS * PH;  // 16,777,216
    const size_t lastN = (size_t)NSEQ * PH;   //     65,536

    float* hdst;
    float* lastdst = nullptr;
    if ((size_t)out_size >= hN) {
        hdst = out;
        if ((size_t)out_size >= hN + lastN) lastdst = out + hN;
    } else {
        hdst = p_ys;       // output is only h_last
        lastdst = out;
    }

    const float* cur = p_conv;
    int layer0 = 1;
    for (int i = 0; i < PNL; i++) {
        gemm_pre<<<dim3(2, 512), 256>>>(
            cur, W_ih + (size_t)i*PH*PD, r + (size_t)i*PE*PD,
            s + (size_t)i*PE*PH, b + (size_t)i*PH, p_pre, layer0);
        float* ysdst = (i == PNL-1) ? hdst : p_ys;
        float* ldst  = (i == PNL-1) ? lastdst : nullptr;
        rnn_kernel<<<NSEQ/2, 256, RNN_SMEM>>>(
            p_pre, p_whhT + (size_t)i*PH*PH, ysdst, ldst);
        cur = ysdst;
        layer0 = 0;
    }
}